// round 3
// baseline (speedup 1.0000x reference)
#include <cuda_runtime.h>
#include <cstdint>

// SJLT scatter projection.
// out[b, p] = (1/sqrt(c)) * sum_{d, j : idx[d,j]==p} sign[d,j] * x[b, d]
//
// Strategy: 148 CTAs = 37 D-chunks x 4 batch-groups (8 batches each).
// Each CTA privatizes acc[8][4096] fp32 in SMEM (128 KB), scatter-adds with
// shared-memory atomics, then stores its partial to a static __device__
// scratch. A tiny second kernel sums the 37 chunk-partials and scales.

#define NCHUNK 37
#define NGROUP 4
#define BDIM   512
#define PDIM   4096
#define CDIM   8
#define BPG    8          // batches per group
#define BTOT   32

// 37 * 32 * 4096 floats = ~19.4 MB static scratch (allocation-free rule).
__device__ float g_partial[(size_t)NCHUNK * BTOT * PDIM];

extern __shared__ float s_acc[];   // BPG * PDIM = 32768 floats = 128 KB

__global__ __launch_bounds__(BDIM, 1)
void sjlt_scatter(const float* __restrict__ x,
                  const int4*  __restrict__ idx4,
                  const int4*  __restrict__ sgn4,
                  int D, int chunkSz)
{
    const int chunk = blockIdx.x >> 2;   // 0..36
    const int g     = blockIdx.x & 3;    // 0..3

    // zero the private accumulator
    for (int i = threadIdx.x; i < BPG * PDIM; i += BDIM)
        s_acc[i] = 0.0f;
    __syncthreads();

    const int d0 = chunk * chunkSz;
    const int d1 = min(D, d0 + chunkSz);
    const float* xb = x + (size_t)g * BPG * D;

    for (int d = d0 + threadIdx.x; d < d1; d += BDIM) {
        // 8 indices + 8 signs for this d (two int4 loads each, coalesced)
        const int4 ia = idx4[2 * d];
        const int4 ib = idx4[2 * d + 1];
        const int4 sa = sgn4[2 * d];
        const int4 sb = sgn4[2 * d + 1];

        // 8 batch values for this d (coalesced streams; evict-first so the
        // idx/sign working set survives in L2 for the sibling group-CTAs)
        unsigned xv[BPG];
        #pragma unroll
        for (int b = 0; b < BPG; b++)
            xv[b] = __float_as_uint(__ldcs(xb + (size_t)b * D + d));

        int pj[CDIM] = {ia.x, ia.y, ia.z, ia.w, ib.x, ib.y, ib.z, ib.w};
        int sj[CDIM] = {sa.x, sa.y, sa.z, sa.w, sb.x, sb.y, sb.z, sb.w};

        #pragma unroll
        for (int j = 0; j < CDIM; j++) {
            // sign in {-1,+1}: -1 = 0xFFFFFFFF -> flip sign bit via XOR (LOP3)
            const unsigned flip = ((unsigned)sj[j]) & 0x80000000u;
            float* a = s_acc + pj[j];          // layout acc[b][p] = b*PDIM + p
            #pragma unroll
            for (int b = 0; b < BPG; b++)
                atomicAdd(a + b * PDIM, __uint_as_float(xv[b] ^ flip));
        }
    }
    __syncthreads();

    // flush private accumulator to scratch: partial[chunk][g*8 + b][p]
    float* dst = g_partial + ((size_t)chunk * BTOT + (size_t)g * BPG) * PDIM;
    for (int i = threadIdx.x; i < BPG * PDIM; i += BDIM)
        dst[i] = s_acc[i];
}

__global__ void sjlt_reduce(float* __restrict__ out)
{
    const int i = blockIdx.x * blockDim.x + threadIdx.x;  // 0..131071
    float s = 0.0f;
    #pragma unroll
    for (int c = 0; c < NCHUNK; c++)
        s += g_partial[(size_t)c * (BTOT * PDIM) + i];
    out[i] = s * 0.35355339059327373f;   // 1/sqrt(8)
}

extern "C" void kernel_launch(void* const* d_in, const int* in_sizes, int n_in,
                              void* d_out, int out_size)
{
    const float* x    = (const float*)d_in[0];
    const int4*  idx4 = (const int4*) d_in[1];
    const int4*  sgn4 = (const int4*) d_in[2];

    const int D       = in_sizes[1] / CDIM;           // 1,000,000
    const int chunkSz = (D + NCHUNK - 1) / NCHUNK;    // 27,028

    // opt-in to 128 KB dynamic SMEM (idempotent, host-side, capture-safe)
    cudaFuncSetAttribute(sjlt_scatter,
                         cudaFuncAttributeMaxDynamicSharedMemorySize,
                         BPG * PDIM * (int)sizeof(float));

    sjlt_scatter<<<NCHUNK * NGROUP, BDIM, BPG * PDIM * sizeof(float)>>>(
        x, idx4, sgn4, D, chunkSz);

    sjlt_reduce<<<(BTOT * PDIM) / 256, 256>>>((float*)d_out);
}